// round 1
// baseline (speedup 1.0000x reference)
#include <cuda_runtime.h>
#include <math.h>

#define BATCH 2
#define NT    2048
#define NSEG1 1536
#define NSEG2 512
#define DM    1024
#define NH    16
#define HD    64

// Scratch (static device arrays — no allocation)
static __device__ float g_qkv[BATCH * NT * 3 * DM];   // (b, n, 3*1024) post-GEMM
static __device__ float g_q[BATCH * NH * NT * HD];    // (b, h, n, d)
static __device__ float g_k[BATCH * NH * NT * HD];
static __device__ float g_v[BATCH * NH * NT * HD];
static __device__ float g_x[BATCH * NT * DM];         // attention out, (b, n, h*d)

// ---------------------------------------------------------------------------
// Fast exp on the FMA pipe (avoids MUFU: rt=8/SMSP would bottleneck softmax)
// valid for x <= 0, rel err ~2e-6
// ---------------------------------------------------------------------------
__device__ __forceinline__ float fexp(float x) {
    x = fmaxf(x, -80.0f);
    float t = x * 1.4426950408889634f;
    float n = rintf(t);
    float f = t - n;
    float z = f * 0.6931471805599453f;
    float p = 1.0f + z * (1.0f + z * (0.5f + z * (0.16666667f + z * (0.041666667f + z * 0.008333334f))));
    int ni = (int)n;
    float s = __int_as_float((ni + 127) << 23);
    return p * s;
}

// ---------------------------------------------------------------------------
// Generic NT GEMM: C[m, n] = sum_k A[m, k] * B[n, k] + bias[n]
// A rows may be batched with a stride (for reading slices of g_x / writing
// slices of g_qkv). 128x128x16 tiles, 256 threads, 8x8 micro-tile.
// ---------------------------------------------------------------------------
#define GBM 128
#define GBN 128
#define GBK 16

__global__ void __launch_bounds__(256, 2)
gemm_nt(const float* __restrict__ A, const float* __restrict__ B,
        const float* __restrict__ bias, float* __restrict__ C,
        int M, int N, int K,
        int aRPB, long long aBS,      // A rows-per-batch, batch stride (elems)
        int cRPB, long long cBS)      // C rows-per-batch, batch stride (elems)
{
    __shared__ float As[GBK][GBM];
    __shared__ float Bs[GBK][GBN];

    const int tid = threadIdx.x;
    const int tx = tid & 15;        // 0..15 -> 8 cols each
    const int ty = tid >> 4;        // 0..15 -> 8 rows each
    const int m0 = blockIdx.y * GBM;
    const int n0 = blockIdx.x * GBN;

    // load mapping: 2 float4 per thread per operand (row lr, k-chunk of 8)
    const int lr = tid >> 1;          // 0..127
    const int lg = (tid & 1) * 2;     // float4-group 0 or 2

    const int am = m0 + lr;
    const int ab = am / aRPB;
    const float* Arow = A + (long long)ab * aBS + (long long)(am - ab * aRPB) * K;
    const float* Brow = B + (long long)(n0 + lr) * K;

    float acc[8][8];
#pragma unroll
    for (int i = 0; i < 8; i++)
#pragma unroll
        for (int j = 0; j < 8; j++) acc[i][j] = 0.0f;

    for (int k0 = 0; k0 < K; k0 += GBK) {
        float4 a0 = *(const float4*)(Arow + k0 + 4 * lg);
        float4 a1 = *(const float4*)(Arow + k0 + 4 * lg + 4);
        float4 b0 = *(const float4*)(Brow + k0 + 4 * lg);
        float4 b1 = *(const float4*)(Brow + k0 + 4 * lg + 4);
        __syncthreads();
        As[4 * lg + 0][lr] = a0.x; As[4 * lg + 1][lr] = a0.y;
        As[4 * lg + 2][lr] = a0.z; As[4 * lg + 3][lr] = a0.w;
        As[4 * lg + 4][lr] = a1.x; As[4 * lg + 5][lr] = a1.y;
        As[4 * lg + 6][lr] = a1.z; As[4 * lg + 7][lr] = a1.w;
        Bs[4 * lg + 0][lr] = b0.x; Bs[4 * lg + 1][lr] = b0.y;
        Bs[4 * lg + 2][lr] = b0.z; Bs[4 * lg + 3][lr] = b0.w;
        Bs[4 * lg + 4][lr] = b1.x; Bs[4 * lg + 5][lr] = b1.y;
        Bs[4 * lg + 6][lr] = b1.z; Bs[4 * lg + 7][lr] = b1.w;
        __syncthreads();

#pragma unroll
        for (int kk = 0; kk < GBK; kk++) {
            float4 av0 = *(const float4*)&As[kk][8 * ty];
            float4 av1 = *(const float4*)&As[kk][8 * ty + 4];
            float4 bv0 = *(const float4*)&Bs[kk][8 * tx];
            float4 bv1 = *(const float4*)&Bs[kk][8 * tx + 4];
            float ar[8] = {av0.x, av0.y, av0.z, av0.w, av1.x, av1.y, av1.z, av1.w};
            float br[8] = {bv0.x, bv0.y, bv0.z, bv0.w, bv1.x, bv1.y, bv1.z, bv1.w};
#pragma unroll
            for (int i = 0; i < 8; i++)
#pragma unroll
                for (int j = 0; j < 8; j++)
                    acc[i][j] += ar[i] * br[j];
        }
    }

    float4 bia = *(const float4*)&bias[n0 + 8 * tx];
    float4 bib = *(const float4*)&bias[n0 + 8 * tx + 4];
#pragma unroll
    for (int i = 0; i < 8; i++) {
        int row = m0 + 8 * ty + i;
        int cb = row / cRPB;
        float* Crow = C + (long long)cb * cBS + (long long)(row - cb * cRPB) * N;
        float4 o0 = make_float4(acc[i][0] + bia.x, acc[i][1] + bia.y,
                                acc[i][2] + bia.z, acc[i][3] + bia.w);
        float4 o1 = make_float4(acc[i][4] + bib.x, acc[i][5] + bib.y,
                                acc[i][6] + bib.z, acc[i][7] + bib.w);
        *(float4*)&Crow[n0 + 8 * tx] = o0;
        *(float4*)&Crow[n0 + 8 * tx + 4] = o1;
    }
}

// ---------------------------------------------------------------------------
// Split QKV + RMSNorm + RoPE. One warp per (b, n, head); lane handles pair
// (2*lane, 2*lane+1), which is exactly one RoPE pair.
// ---------------------------------------------------------------------------
__global__ void __launch_bounds__(256)
qkv_post(const float* __restrict__ qs1, const float* __restrict__ ks1,
         const float* __restrict__ qs2, const float* __restrict__ ks2)
{
    int w = (blockIdx.x * blockDim.x + threadIdx.x) >> 5;
    int lane = threadIdx.x & 31;
    int h = w & 15;
    int n = (w >> 4) & (NT - 1);
    int b = w >> 15;

    const float* row = g_qkv + (long long)(b * NT + n) * (3 * DM);
    const float* qs = (n < NSEG1) ? qs1 : qs2;
    const float* ks = (n < NSEG1) ? ks1 : ks2;

    float pos = (float)n;
    float e = (float)(2 * lane) * (1.0f / 64.0f);
    float invf = expf(-e * 9.210340371976184f);   // ln(10000)
    float ang = pos * invf;
    float cs = cosf(ang), sn = sinf(ang);

    long long obase = ((long long)(b * NH + h) * NT + n) * HD + 2 * lane;
    int doff = h * HD + 2 * lane;

    // Q
    {
        float2 v = *(const float2*)(row + doff);
        float ss = v.x * v.x + v.y * v.y;
#pragma unroll
        for (int off = 16; off; off >>= 1) ss += __shfl_xor_sync(0xffffffffu, ss, off);
        float inv = rsqrtf(ss * (1.0f / 64.0f) + 1e-6f);
        float a = v.x * inv * qs[2 * lane];
        float c = v.y * inv * qs[2 * lane + 1];
        float2 o = make_float2(a * cs - c * sn, a * sn + c * cs);
        *(float2*)(g_q + obase) = o;
    }
    // K
    {
        float2 v = *(const float2*)(row + DM + doff);
        float ss = v.x * v.x + v.y * v.y;
#pragma unroll
        for (int off = 16; off; off >>= 1) ss += __shfl_xor_sync(0xffffffffu, ss, off);
        float inv = rsqrtf(ss * (1.0f / 64.0f) + 1e-6f);
        float a = v.x * inv * ks[2 * lane];
        float c = v.y * inv * ks[2 * lane + 1];
        float2 o = make_float2(a * cs - c * sn, a * sn + c * cs);
        *(float2*)(g_k + obase) = o;
    }
    // V (plain copy into (b,h,n,d))
    {
        float2 v = *(const float2*)(row + 2 * DM + doff);
        *(float2*)(g_v + obase) = v;
    }
}

// ---------------------------------------------------------------------------
// Flash attention: block = (b, h, 64-query tile). 256 threads (16x16),
// 4x4 micro-tiles. Softmax state (m, l) lives in registers, replicated
// across the 16 lanes that own one row; reductions via shfl within the
// 16-lane half-warp group. K-tile smem is reused to hold P.
// Q is pre-scaled by 1/8 at load.
// ---------------------------------------------------------------------------
__global__ void __launch_bounds__(256, 3)
flash_attn()
{
    __shared__ float Qs[64 * 64];   // [d][r]
    __shared__ float KPs[64 * 64];  // K as [d][c], then P as [k][r]
    __shared__ float Vs[64 * 64];   // [k][d]

    const int b = blockIdx.z, h = blockIdx.y;
    const int q0 = blockIdx.x * 64;
    const int tid = threadIdx.x;
    const int tx = tid & 15, ty = tid >> 4;

    const long long bh = (long long)(b * NH + h) * NT;
    const float* Qbase = g_q + bh * HD;
    const float* Kbase = g_k + bh * HD;
    const float* Vbase = g_v + bh * HD;

    const int lr = tid >> 2;        // 0..63 row
    const int lg = tid & 3;         // 16-float d-chunk

    // Load Q tile transposed, pre-scaled by softmax scale 1/8
    {
        const float* qrow = Qbase + (long long)(q0 + lr) * HD + lg * 16;
#pragma unroll
        for (int j = 0; j < 4; j++) {
            float4 v = *(const float4*)(qrow + 4 * j);
            int d = lg * 16 + 4 * j;
            Qs[(d + 0) * 64 + lr] = v.x * 0.125f;
            Qs[(d + 1) * 64 + lr] = v.y * 0.125f;
            Qs[(d + 2) * 64 + lr] = v.z * 0.125f;
            Qs[(d + 3) * 64 + lr] = v.w * 0.125f;
        }
    }

    float o[4][4];
    float mreg[4], lreg[4];
#pragma unroll
    for (int i = 0; i < 4; i++) {
        mreg[i] = -1e30f; lreg[i] = 0.0f;
#pragma unroll
        for (int j = 0; j < 4; j++) o[i][j] = 0.0f;
    }

    for (int kt = 0; kt < NT; kt += 64) {
        // Load K transposed, V natural
        {
            const float* krow = Kbase + (long long)(kt + lr) * HD + lg * 16;
            const float* vrow = Vbase + (long long)(kt + lr) * HD + lg * 16;
#pragma unroll
            for (int j = 0; j < 4; j++) {
                float4 kv = *(const float4*)(krow + 4 * j);
                int d = lg * 16 + 4 * j;
                KPs[(d + 0) * 64 + lr] = kv.x;
                KPs[(d + 1) * 64 + lr] = kv.y;
                KPs[(d + 2) * 64 + lr] = kv.z;
                KPs[(d + 3) * 64 + lr] = kv.w;
                float4 vv = *(const float4*)(vrow + 4 * j);
                *(float4*)&Vs[lr * 64 + d] = vv;
            }
        }
        __syncthreads();

        // S = Q^T K (per-thread 4x4)
        float s[4][4];
#pragma unroll
        for (int i = 0; i < 4; i++)
#pragma unroll
            for (int j = 0; j < 4; j++) s[i][j] = 0.0f;
#pragma unroll 16
        for (int d = 0; d < 64; d++) {
            float4 aa = *(const float4*)&Qs[d * 64 + 4 * ty];
            float4 bb = *(const float4*)&KPs[d * 64 + 4 * tx];
            float ar[4] = {aa.x, aa.y, aa.z, aa.w};
            float br[4] = {bb.x, bb.y, bb.z, bb.w};
#pragma unroll
            for (int i = 0; i < 4; i++)
#pragma unroll
                for (int j = 0; j < 4; j++)
                    s[i][j] += ar[i] * br[j];
        }
        __syncthreads();   // everyone done reading K; KPs may be overwritten

        // Online softmax (row state in registers, shfl over 16-lane groups)
#pragma unroll
        for (int i = 0; i < 4; i++) {
            float mt = fmaxf(fmaxf(s[i][0], s[i][1]), fmaxf(s[i][2], s[i][3]));
#pragma unroll
            for (int off = 8; off; off >>= 1) mt = fmaxf(mt, __shfl_xor_sync(0xffffffffu, mt, off));
            float nm = fmaxf(mreg[i], mt);
            float f = fexp(mreg[i] - nm);
            mreg[i] = nm;
            float ts = 0.0f;
            float p[4];
#pragma unroll
            for (int j = 0; j < 4; j++) {
                p[j] = fexp(s[i][j] - nm);
                ts += p[j];
            }
#pragma unroll
            for (int off = 8; off; off >>= 1) ts += __shfl_xor_sync(0xffffffffu, ts, off);
            lreg[i] = lreg[i] * f + ts;
#pragma unroll
            for (int j = 0; j < 4; j++) {
                o[i][j] *= f;
                KPs[(4 * tx + j) * 64 + 4 * ty + i] = p[j];   // P^T: [k][r]
            }
        }
        __syncthreads();   // P visible

        // O += P V
#pragma unroll 16
        for (int k = 0; k < 64; k++) {
            float4 aa = *(const float4*)&KPs[k * 64 + 4 * ty];
            float4 bb = *(const float4*)&Vs[k * 64 + 4 * tx];
            float ar[4] = {aa.x, aa.y, aa.z, aa.w};
            float br[4] = {bb.x, bb.y, bb.z, bb.w};
#pragma unroll
            for (int i = 0; i < 4; i++)
#pragma unroll
                for (int j = 0; j < 4; j++)
                    o[i][j] += ar[i] * br[j];
        }
        __syncthreads();   // before next tile's loads overwrite KPs/Vs
    }

    // Finalize and write x in (b, n, h*64 + d) layout
#pragma unroll
    for (int i = 0; i < 4; i++) {
        float inv = 1.0f / lreg[i];
        int row = q0 + 4 * ty + i;
        float4 ov = make_float4(o[i][0] * inv, o[i][1] * inv, o[i][2] * inv, o[i][3] * inv);
        *(float4*)&g_x[((long long)b * NT + row) * DM + h * HD + 4 * tx] = ov;
    }
}

// ---------------------------------------------------------------------------
// Launch
// ---------------------------------------------------------------------------
extern "C" void kernel_launch(void* const* d_in, const int* in_sizes, int n_in,
                              void* d_out, int out_size)
{
    const float* x1  = (const float*)d_in[0];
    const float* x2  = (const float*)d_in[1];
    const float* Wq1 = (const float*)d_in[2];
    const float* bq1 = (const float*)d_in[3];
    const float* Wq2 = (const float*)d_in[4];
    const float* bq2 = (const float*)d_in[5];
    const float* Wo1 = (const float*)d_in[6];
    const float* bo1 = (const float*)d_in[7];
    const float* Wo2 = (const float*)d_in[8];
    const float* bo2 = (const float*)d_in[9];
    const float* qs1 = (const float*)d_in[10];
    const float* ks1 = (const float*)d_in[11];
    const float* qs2 = (const float*)d_in[12];
    const float* ks2 = (const float*)d_in[13];
    float* out = (float*)d_out;

    float *qkv, *xbuf;
    cudaGetSymbolAddress((void**)&qkv, g_qkv);
    cudaGetSymbolAddress((void**)&xbuf, g_x);

    // QKV projections into combined (b, 2048, 3072) scratch
    gemm_nt<<<dim3(3072 / GBN, 3072 / GBM), 256>>>(
        x1, Wq1, bq1, qkv,
        3072, 3072, 1024,
        NSEG1, (long long)NSEG1 * DM,
        NSEG1, (long long)NT * 3 * DM);
    gemm_nt<<<dim3(3072 / GBN, 1024 / GBM), 256>>>(
        x2, Wq2, bq2, qkv + (long long)NSEG1 * 3 * DM,
        1024, 3072, 1024,
        NSEG2, (long long)NSEG2 * DM,
        NSEG2, (long long)NT * 3 * DM);

    // Split + RMSNorm + RoPE -> g_q/g_k/g_v
    qkv_post<<<(BATCH * NT * NH) / 8, 256>>>(qs1, ks1, qs2, ks2);

    // Attention -> g_x
    flash_attn<<<dim3(NT / 64, NH, BATCH), 256>>>();

    // Output projections (out1 then out2, concatenated in d_out)
    gemm_nt<<<dim3(1024 / GBN, 3072 / GBM), 256>>>(
        xbuf, Wo1, bo1, out,
        3072, 1024, 1024,
        NSEG1, (long long)NT * DM,
        NSEG1, (long long)NSEG1 * DM);
    gemm_nt<<<dim3(1024 / GBN, 1024 / GBM), 256>>>(
        xbuf + (long long)NSEG1 * DM, Wo2, bo2, out + (long long)BATCH * NSEG1 * DM,
        1024, 1024, 1024,
        NSEG2, (long long)NT * DM,
        NSEG2, (long long)NSEG2 * DM);
}

// round 2
// speedup vs baseline: 1.1703x; 1.1703x over previous
#include <cuda_runtime.h>
#include <math.h>

#define BATCH 2
#define NT    2048
#define NSEG1 1536
#define NSEG2 512
#define DM    1024
#define NH    16
#define HD    64

typedef unsigned long long u64;

// Scratch (static device arrays — no allocation)
static __device__ float g_qkv[BATCH * NT * 3 * DM];   // (b, n, 3*1024) post-GEMM
static __device__ float g_q[BATCH * NH * NT * HD];    // (b, h, n, d)
static __device__ float g_k[BATCH * NH * NT * HD];
static __device__ float g_v[BATCH * NH * NT * HD];
static __device__ float g_x[BATCH * NT * DM];         // attention out, (b, n, h*d)

// ---------------------------------------------------------------------------
// Packed fp32 (Blackwell FFMA2) helpers — ptxas never auto-fuses these.
// ---------------------------------------------------------------------------
__device__ __forceinline__ u64 ffma2(u64 a, u64 b, u64 c) {
    u64 d;
    asm("fma.rn.f32x2 %0, %1, %2, %3;" : "=l"(d) : "l"(a), "l"(b), "l"(c));
    return d;
}
__device__ __forceinline__ u64 fmul2(u64 a, u64 b) {
    u64 d;
    asm("mul.rn.f32x2 %0, %1, %2;" : "=l"(d) : "l"(a), "l"(b));
    return d;
}
__device__ __forceinline__ u64 bcast2(float x) {
    u64 r;
    asm("mov.b64 %0, {%1, %1};" : "=l"(r) : "f"(x));
    return r;
}
__device__ __forceinline__ float2 unpack2(u64 v) {
    float2 f;
    asm("mov.b64 {%0, %1}, %2;" : "=f"(f.x), "=f"(f.y) : "l"(v));
    return f;
}

// ---------------------------------------------------------------------------
// Fast exp on the FMA pipe (avoids MUFU rt=8 bottleneck); valid x <= 0
// ---------------------------------------------------------------------------
__device__ __forceinline__ float fexp(float x) {
    x = fmaxf(x, -80.0f);
    float t = x * 1.4426950408889634f;
    float n = rintf(t);
    float f = t - n;
    float z = f * 0.6931471805599453f;
    float p = 1.0f + z * (1.0f + z * (0.5f + z * (0.16666667f + z * (0.041666667f + z * 0.008333334f))));
    int ni = (int)n;
    float s = __int_as_float((ni + 127) << 23);
    return p * s;
}

// ---------------------------------------------------------------------------
// NT GEMM: C[m, n] = sum_k A[m, k] * B[n, k] + bias[n]
// 128x128x16 tiles, 256 threads, 8x8 micro-tile with split-4 mapping
// (rows {4ty, 64+4ty}, cols {4tx, 64+4tx}) -> conflict-free LDS.128.
// Inner loop uses packed fma.rn.f32x2.
// ---------------------------------------------------------------------------
#define GBM 128
#define GBN 128
#define GBK 16

__global__ void __launch_bounds__(256, 2)
gemm_nt(const float* __restrict__ A, const float* __restrict__ B,
        const float* __restrict__ bias, float* __restrict__ C,
        int M, int N, int K,
        int aRPB, long long aBS,      // A rows-per-batch, batch stride (elems)
        int cRPB, long long cBS)      // C rows-per-batch, batch stride (elems)
{
    __shared__ float As[GBK][GBM];
    __shared__ float Bs[GBK][GBN];

    const int tid = threadIdx.x;
    const int tx = tid & 15;        // col groups {4tx, 64+4tx}
    const int ty = tid >> 4;        // row groups {4ty, 64+4ty}
    const int m0 = blockIdx.y * GBM;
    const int n0 = blockIdx.x * GBN;

    const int lr = tid >> 1;          // 0..127
    const int lg = (tid & 1) * 2;     // float4-group 0 or 2

    const int am = m0 + lr;
    const int ab = am / aRPB;
    const float* Arow = A + (long long)ab * aBS + (long long)(am - ab * aRPB) * K;
    const float* Brow = B + (long long)(n0 + lr) * K;

    u64 acc[8][4];
#pragma unroll
    for (int i = 0; i < 8; i++)
#pragma unroll
        for (int j = 0; j < 4; j++) acc[i][j] = 0ull;

    for (int k0 = 0; k0 < K; k0 += GBK) {
        float4 a0 = *(const float4*)(Arow + k0 + 4 * lg);
        float4 a1 = *(const float4*)(Arow + k0 + 4 * lg + 4);
        float4 b0 = *(const float4*)(Brow + k0 + 4 * lg);
        float4 b1 = *(const float4*)(Brow + k0 + 4 * lg + 4);
        __syncthreads();
        As[4 * lg + 0][lr] = a0.x; As[4 * lg + 1][lr] = a0.y;
        As[4 * lg + 2][lr] = a0.z; As[4 * lg + 3][lr] = a0.w;
        As[4 * lg + 4][lr] = a1.x; As[4 * lg + 5][lr] = a1.y;
        As[4 * lg + 6][lr] = a1.z; As[4 * lg + 7][lr] = a1.w;
        Bs[4 * lg + 0][lr] = b0.x; Bs[4 * lg + 1][lr] = b0.y;
        Bs[4 * lg + 2][lr] = b0.z; Bs[4 * lg + 3][lr] = b0.w;
        Bs[4 * lg + 4][lr] = b1.x; Bs[4 * lg + 5][lr] = b1.y;
        Bs[4 * lg + 6][lr] = b1.z; Bs[4 * lg + 7][lr] = b1.w;
        __syncthreads();

#pragma unroll
        for (int kk = 0; kk < GBK; kk++) {
            float4 av0 = *(const float4*)&As[kk][4 * ty];
            float4 av1 = *(const float4*)&As[kk][64 + 4 * ty];
            ulonglong2 bv0 = *(const ulonglong2*)&Bs[kk][4 * tx];
            ulonglong2 bv1 = *(const ulonglong2*)&Bs[kk][64 + 4 * tx];
            float ar[8] = {av0.x, av0.y, av0.z, av0.w, av1.x, av1.y, av1.z, av1.w};
            u64 br[4] = {bv0.x, bv0.y, bv1.x, bv1.y};
#pragma unroll
            for (int i = 0; i < 8; i++) {
                u64 ai = bcast2(ar[i]);
#pragma unroll
                for (int j = 0; j < 4; j++)
                    acc[i][j] = ffma2(ai, br[j], acc[i][j]);
            }
        }
    }

    float4 biA = *(const float4*)&bias[n0 + 4 * tx];
    float4 biB = *(const float4*)&bias[n0 + 64 + 4 * tx];
#pragma unroll
    for (int i = 0; i < 8; i++) {
        int row = m0 + ((i < 4) ? (4 * ty + i) : (64 + 4 * ty + i - 4));
        int cb = row / cRPB;
        float* Crow = C + (long long)cb * cBS + (long long)(row - cb * cRPB) * N;
        float2 p0 = unpack2(acc[i][0]);
        float2 p1 = unpack2(acc[i][1]);
        float2 p2 = unpack2(acc[i][2]);
        float2 p3 = unpack2(acc[i][3]);
        float4 oA = make_float4(p0.x + biA.x, p0.y + biA.y, p1.x + biA.z, p1.y + biA.w);
        float4 oB = make_float4(p2.x + biB.x, p2.y + biB.y, p3.x + biB.z, p3.y + biB.w);
        *(float4*)&Crow[n0 + 4 * tx] = oA;
        *(float4*)&Crow[n0 + 64 + 4 * tx] = oB;
    }
}

// ---------------------------------------------------------------------------
// Split QKV + RMSNorm + RoPE. One warp per (b, n, head).
// ---------------------------------------------------------------------------
__global__ void __launch_bounds__(256)
qkv_post(const float* __restrict__ qs1, const float* __restrict__ ks1,
         const float* __restrict__ qs2, const float* __restrict__ ks2)
{
    int w = (blockIdx.x * blockDim.x + threadIdx.x) >> 5;
    int lane = threadIdx.x & 31;
    int h = w & 15;
    int n = (w >> 4) & (NT - 1);
    int b = w >> 15;

    const float* row = g_qkv + (long long)(b * NT + n) * (3 * DM);
    const float* qs = (n < NSEG1) ? qs1 : qs2;
    const float* ks = (n < NSEG1) ? ks1 : ks2;

    float pos = (float)n;
    float e = (float)(2 * lane) * (1.0f / 64.0f);
    float invf = expf(-e * 9.210340371976184f);   // ln(10000)
    float ang = pos * invf;
    float cs = cosf(ang), sn = sinf(ang);

    long long obase = ((long long)(b * NH + h) * NT + n) * HD + 2 * lane;
    int doff = h * HD + 2 * lane;

    // Q
    {
        float2 v = *(const float2*)(row + doff);
        float ss = v.x * v.x + v.y * v.y;
#pragma unroll
        for (int off = 16; off; off >>= 1) ss += __shfl_xor_sync(0xffffffffu, ss, off);
        float inv = rsqrtf(ss * (1.0f / 64.0f) + 1e-6f);
        float a = v.x * inv * qs[2 * lane];
        float c = v.y * inv * qs[2 * lane + 1];
        float2 o = make_float2(a * cs - c * sn, a * sn + c * cs);
        *(float2*)(g_q + obase) = o;
    }
    // K
    {
        float2 v = *(const float2*)(row + DM + doff);
        float ss = v.x * v.x + v.y * v.y;
#pragma unroll
        for (int off = 16; off; off >>= 1) ss += __shfl_xor_sync(0xffffffffu, ss, off);
        float inv = rsqrtf(ss * (1.0f / 64.0f) + 1e-6f);
        float a = v.x * inv * ks[2 * lane];
        float c = v.y * inv * ks[2 * lane + 1];
        float2 o = make_float2(a * cs - c * sn, a * sn + c * cs);
        *(float2*)(g_k + obase) = o;
    }
    // V
    {
        float2 v = *(const float2*)(row + 2 * DM + doff);
        *(float2*)(g_v + obase) = v;
    }
}

// ---------------------------------------------------------------------------
// Flash attention v2: 128 q-rows x 128 k-cols per tile, 256 threads.
// QK: 8x8 micro (split-4), PV: 8x4 micro, all packed fma.rn.f32x2.
// P stored transposed with XOR swizzle (r ^ (k & 0x1C)) -> low-conflict
// scalar stores, conflict-free quad reads. V padded to stride 68.
// Dynamic smem 162 KB -> 1 CTA/SM (FMA-bound; 8 warps suffice).
// ---------------------------------------------------------------------------
#define FA_QS   0                      // Qs[d][r]    : 64 x 128
#define FA_KS   (64 * 128)             // Ks[d][c]    : 64 x 128
#define FA_VS   (2 * 64 * 128)         // Vs[k][d]    : 128 x 68 (padded)
#define FA_PS   (2 * 64 * 128 + 128 * 68)  // Ps[k][r^] : 128 x 128
#define FA_SMEM_FLOATS (FA_PS + 128 * 128)
#define FA_SMEM_BYTES  (FA_SMEM_FLOATS * 4)

__global__ void __launch_bounds__(256, 1)
flash_attn()
{
    extern __shared__ float sm[];
    float* Qs = sm + FA_QS;
    float* Ks = sm + FA_KS;
    float* Vs = sm + FA_VS;
    float* Ps = sm + FA_PS;

    const int b = blockIdx.z, h = blockIdx.y;
    const int q0 = blockIdx.x * 128;
    const int tid = threadIdx.x;
    const int tx = tid & 15, ty = tid >> 4;

    const long long bh = (long long)(b * NH + h) * NT;
    const float* Qbase = g_q + bh * HD;
    const float* Kbase = g_k + bh * HD;
    const float* Vbase = g_v + bh * HD;

    const int lr = tid >> 1;        // 0..127 (row)
    const int lg = tid & 1;         // half of d (32 floats)

    // Load Q tile (128 rows) transposed into Qs[d][r], pre-scaled by 1/8
    {
        const float* qrow = Qbase + (long long)(q0 + lr) * HD + lg * 32;
#pragma unroll
        for (int c = 0; c < 8; c++) {
            float4 v = *(const float4*)(qrow + 4 * c);
            int d = lg * 32 + 4 * c;
            Qs[(d + 0) * 128 + lr] = v.x * 0.125f;
            Qs[(d + 1) * 128 + lr] = v.y * 0.125f;
            Qs[(d + 2) * 128 + lr] = v.z * 0.125f;
            Qs[(d + 3) * 128 + lr] = v.w * 0.125f;
        }
    }

    u64 oacc[8][2];
    float mreg[8], lreg[8];
#pragma unroll
    for (int i = 0; i < 8; i++) {
        mreg[i] = -1e30f; lreg[i] = 0.0f;
        oacc[i][0] = 0ull; oacc[i][1] = 0ull;
    }

    for (int kt = 0; kt < NT; kt += 128) {
        // Global loads for this tile (issued before the barrier)
        float4 kvr[8], vvr[8];
        {
            const float* krow = Kbase + (long long)(kt + lr) * HD + lg * 32;
            const float* vrow = Vbase + (long long)(kt + lr) * HD + lg * 32;
#pragma unroll
            for (int c = 0; c < 8; c++) {
                kvr[c] = *(const float4*)(krow + 4 * c);
                vvr[c] = *(const float4*)(vrow + 4 * c);
            }
        }
        __syncthreads();   // prev iter's QK/PV reads of Ks/Vs done
        {
#pragma unroll
            for (int c = 0; c < 8; c++) {
                int d = lg * 32 + 4 * c;
                Ks[(d + 0) * 128 + lr] = kvr[c].x;
                Ks[(d + 1) * 128 + lr] = kvr[c].y;
                Ks[(d + 2) * 128 + lr] = kvr[c].z;
                Ks[(d + 3) * 128 + lr] = kvr[c].w;
                *(float4*)&Vs[lr * 68 + d] = vvr[c];
            }
        }
        __syncthreads();

        // S = Q^T K : 8x8 micro (rows {4ty, 64+4ty}, cols {4tx, 64+4tx})
        u64 sacc[8][4];
#pragma unroll
        for (int i = 0; i < 8; i++)
#pragma unroll
            for (int j = 0; j < 4; j++) sacc[i][j] = 0ull;

#pragma unroll 8
        for (int d = 0; d < 64; d++) {
            float4 av0 = *(const float4*)&Qs[d * 128 + 4 * ty];
            float4 av1 = *(const float4*)&Qs[d * 128 + 64 + 4 * ty];
            ulonglong2 bv0 = *(const ulonglong2*)&Ks[d * 128 + 4 * tx];
            ulonglong2 bv1 = *(const ulonglong2*)&Ks[d * 128 + 64 + 4 * tx];
            float ar[8] = {av0.x, av0.y, av0.z, av0.w, av1.x, av1.y, av1.z, av1.w};
            u64 br[4] = {bv0.x, bv0.y, bv1.x, bv1.y};
#pragma unroll
            for (int i = 0; i < 8; i++) {
                u64 ai = bcast2(ar[i]);
#pragma unroll
                for (int j = 0; j < 4; j++)
                    sacc[i][j] = ffma2(ai, br[j], sacc[i][j]);
            }
        }

        // Online softmax per row (16-lane shfl groups share a row)
#pragma unroll
        for (int i = 0; i < 8; i++) {
            float s[8];
            float2 t;
            t = unpack2(sacc[i][0]); s[0] = t.x; s[1] = t.y;
            t = unpack2(sacc[i][1]); s[2] = t.x; s[3] = t.y;
            t = unpack2(sacc[i][2]); s[4] = t.x; s[5] = t.y;
            t = unpack2(sacc[i][3]); s[6] = t.x; s[7] = t.y;

            float mt = fmaxf(fmaxf(fmaxf(s[0], s[1]), fmaxf(s[2], s[3])),
                             fmaxf(fmaxf(s[4], s[5]), fmaxf(s[6], s[7])));
#pragma unroll
            for (int off = 8; off; off >>= 1) mt = fmaxf(mt, __shfl_xor_sync(0xffffffffu, mt, off));
            float nm = fmaxf(mreg[i], mt);
            float f = fexp(mreg[i] - nm);
            mreg[i] = nm;

            float ts = 0.0f;
            float p[8];
#pragma unroll
            for (int j = 0; j < 8; j++) {
                p[j] = fexp(s[j] - nm);
                ts += p[j];
            }
#pragma unroll
            for (int off = 8; off; off >>= 1) ts += __shfl_xor_sync(0xffffffffu, ts, off);
            lreg[i] = lreg[i] * f + ts;

            u64 f2 = bcast2(f);
            oacc[i][0] = fmul2(oacc[i][0], f2);
            oacc[i][1] = fmul2(oacc[i][1], f2);

            int ri = (i < 4) ? (4 * ty + i) : (64 + 4 * ty + i - 4);
#pragma unroll
            for (int j = 0; j < 8; j++) {
                int kc = (j < 4) ? (4 * tx + j) : (64 + 4 * tx + j - 4);
                Ps[kc * 128 + (ri ^ (kc & 0x1C))] = p[j];
            }
        }
        __syncthreads();   // P visible

        // O += P V : 8 rows x 4 d-cols
#pragma unroll 8
        for (int k = 0; k < 128; k++) {
            int x = k & 0x1C;
            float4 a0 = *(const float4*)&Ps[k * 128 + ((4 * ty) ^ x)];
            float4 a1 = *(const float4*)&Ps[k * 128 + 64 + ((4 * ty) ^ x)];
            ulonglong2 bv = *(const ulonglong2*)&Vs[k * 68 + 4 * tx];
            float ar[8] = {a0.x, a0.y, a0.z, a0.w, a1.x, a1.y, a1.z, a1.w};
#pragma unroll
            for (int i = 0; i < 8; i++) {
                u64 ai = bcast2(ar[i]);
                oacc[i][0] = ffma2(ai, bv.x, oacc[i][0]);
                oacc[i][1] = ffma2(ai, bv.y, oacc[i][1]);
            }
        }
    }

    // Finalize: write x in (b, n, h*64 + d) layout, cols 4tx..4tx+3
#pragma unroll
    for (int i = 0; i < 8; i++) {
        float inv = 1.0f / lreg[i];
        int row = q0 + ((i < 4) ? (4 * ty + i) : (64 + 4 * ty + i - 4));
        float2 p0 = unpack2(oacc[i][0]);
        float2 p1 = unpack2(oacc[i][1]);
        float4 ov = make_float4(p0.x * inv, p0.y * inv, p1.x * inv, p1.y * inv);
        *(float4*)&g_x[((long long)b * NT + row) * DM + h * HD + 4 * tx] = ov;
    }
}

// ---------------------------------------------------------------------------
// Launch
// ---------------------------------------------------------------------------
extern "C" void kernel_launch(void* const* d_in, const int* in_sizes, int n_in,
                              void* d_out, int out_size)
{
    const float* x1  = (const float*)d_in[0];
    const float* x2  = (const float*)d_in[1];
    const float* Wq1 = (const float*)d_in[2];
    const float* bq1 = (const float*)d_in[3];
    const float* Wq2 = (const float*)d_in[4];
    const float* bq2 = (const float*)d_in[5];
    const float* Wo1 = (const float*)d_in[6];
    const float* bo1 = (const float*)d_in[7];
    const float* Wo2 = (const float*)d_in[8];
    const float* bo2 = (const float*)d_in[9];
    const float* qs1 = (const float*)d_in[10];
    const float* ks1 = (const float*)d_in[11];
    const float* qs2 = (const float*)d_in[12];
    const float* ks2 = (const float*)d_in[13];
    float* out = (float*)d_out;

    float *qkv, *xbuf;
    cudaGetSymbolAddress((void**)&qkv, g_qkv);
    cudaGetSymbolAddress((void**)&xbuf, g_x);

    cudaFuncSetAttribute(flash_attn, cudaFuncAttributeMaxDynamicSharedMemorySize,
                         FA_SMEM_BYTES);

    // QKV projections into combined (b, 2048, 3072) scratch
    gemm_nt<<<dim3(3072 / GBN, 3072 / GBM), 256>>>(
        x1, Wq1, bq1, qkv,
        3072, 3072, 1024,
        NSEG1, (long long)NSEG1 * DM,
        NSEG1, (long long)NT * 3 * DM);
    gemm_nt<<<dim3(3072 / GBN, 1024 / GBM), 256>>>(
        x2, Wq2, bq2, qkv + (long long)NSEG1 * 3 * DM,
        1024, 3072, 1024,
        NSEG2, (long long)NSEG2 * DM,
        NSEG2, (long long)NT * 3 * DM);

    // Split + RMSNorm + RoPE -> g_q/g_k/g_v
    qkv_post<<<(BATCH * NT * NH) / 8, 256>>>(qs1, ks1, qs2, ks2);

    // Attention -> g_x
    flash_attn<<<dim3(NT / 128, NH, BATCH), 256, FA_SMEM_BYTES>>>();

    // Output projections (out1 then out2, concatenated in d_out)
    gemm_nt<<<dim3(1024 / GBN, 3072 / GBM), 256>>>(
        xbuf, Wo1, bo1, out,
        3072, 1024, 1024,
        NSEG1, (long long)NT * DM,
        NSEG1, (long long)NSEG1 * DM);
    gemm_nt<<<dim3(1024 / GBN, 1024 / GBM), 256>>>(
        xbuf + (long long)NSEG1 * DM, Wo2, bo2, out + (long long)BATCH * NSEG1 * DM,
        1024, 1024, 1024,
        NSEG2, (long long)NT * DM,
        NSEG2, (long long)NSEG2 * DM);
}